// round 16
// baseline (speedup 1.0000x reference)
#include <cuda_runtime.h>
#include <cuda_bf16.h>
#include <cuda_fp16.h>
#include <math.h>
#include <stdint.h>

// ---------------- problem constants ----------------
#define NL   12
#define BB   4
#define TT   1024
#define CC   768
#define HH   12
#define HS   64
#define VV   50257
#define BT   (BB * TT)
#define C3   (3 * CC)
#define C4   (4 * CC)
#define SCALE 0.125f

#define SZ_Q  (CC * C3)
#define SZ_O  (CC * CC)
#define SZ_1  (CC * C4)
#define SZ_2  (C4 * CC)
#define SZ_ALL ((size_t)NL * (SZ_Q + SZ_O + SZ_1 + SZ_2))

// ---------------- device scratch ----------------
__device__ float g_x[BT * CC];
__device__ __half g_qh[BT * C3];
__device__ __half g_ql[BT * C3];
__device__ __half g_af[BT * CC];
__device__ __half g_ff[BT * C4];
__device__ __half g_wh[SZ_ALL];
__device__ __half g_wl[SZ_ALL];
__device__ __half g_tef[(size_t)VV * CC];

// ---------------- PTX helpers ----------------
__device__ __forceinline__ uint32_t smem_u32(const void* p) {
    uint32_t a;
    asm("{ .reg .u64 t; cvta.to.shared.u64 t, %1; cvt.u32.u64 %0, t; }" : "=r"(a) : "l"(p));
    return a;
}
__device__ __forceinline__ void cp16(uint32_t dst, const void* src, int sz) {
    asm volatile("cp.async.ca.shared.global [%0], [%1], 16, %2;"
                 :: "r"(dst), "l"(src), "r"(sz) : "memory");
}
__device__ __forceinline__ void cp_commit() {
    asm volatile("cp.async.commit_group;" ::: "memory");
}
__device__ __forceinline__ void ldsm4(uint32_t* r, uint32_t a) {
    asm volatile("ldmatrix.sync.aligned.m8n8.x4.shared.b16 {%0,%1,%2,%3}, [%4];"
                 : "=r"(r[0]), "=r"(r[1]), "=r"(r[2]), "=r"(r[3]) : "r"(a));
}
__device__ __forceinline__ void ldsm4t(uint32_t* r, uint32_t a) {
    asm volatile("ldmatrix.sync.aligned.m8n8.x4.trans.shared.b16 {%0,%1,%2,%3}, [%4];"
                 : "=r"(r[0]), "=r"(r[1]), "=r"(r[2]), "=r"(r[3]) : "r"(a));
}
__device__ __forceinline__ void mma_fp16(float* d, const uint32_t* a,
                                         uint32_t b0, uint32_t b1) {
    asm volatile(
        "mma.sync.aligned.m16n8k16.row.col.f32.f16.f16.f32 "
        "{%0,%1,%2,%3}, {%4,%5,%6,%7}, {%8,%9}, {%0,%1,%2,%3};"
        : "+f"(d[0]), "+f"(d[1]), "+f"(d[2]), "+f"(d[3])
        : "r"(a[0]), "r"(a[1]), "r"(a[2]), "r"(a[3]), "r"(b0), "r"(b1));
}
__device__ __forceinline__ uint32_t packhf(float a, float b) {
    __half2 t = __floats2half2_rn(a, b);
    return *reinterpret_cast<uint32_t*>(&t);
}
__device__ __forceinline__ float hfhi(float v) {
    return __half2float(__float2half(v));
}

// ---------------- embedding ----------------
__global__ void embed_kernel(const int* __restrict__ inp,
                             const float* __restrict__ wte,
                             const float* __restrict__ wpe,
                             float* __restrict__ x) {
    int i = blockIdx.x * blockDim.x + threadIdx.x;
    if (i >= BT * CC) return;
    int c = i % CC;
    int bt = i / CC;
    int t = bt % TT;
    int tok = inp[bt];
    x[i] = wte[(size_t)tok * CC + c] + wpe[(size_t)t * CC + c];
}

// ---------------- layernorm (warp per row) -> fp16 ----------------
__global__ void __launch_bounds__(256)
ln_hf_kernel(const float* __restrict__ in,
             const float* __restrict__ g,
             const float* __restrict__ b,
             __half* __restrict__ out) {
    int row = blockIdx.x * 8 + (threadIdx.x >> 5);
    int lane = threadIdx.x & 31;
    const float4* r4 = (const float4*)(in + (size_t)row * CC);

    float4 v[6];
    float s = 0.f;
    #pragma unroll
    for (int i = 0; i < 6; i++) {
        v[i] = r4[lane + i * 32];
        s += v[i].x + v[i].y + v[i].z + v[i].w;
    }
    #pragma unroll
    for (int o = 16; o > 0; o >>= 1) s += __shfl_xor_sync(0xffffffffu, s, o);
    float mu = s / CC;

    float sq = 0.f;
    #pragma unroll
    for (int i = 0; i < 6; i++) {
        float dx = v[i].x - mu, dy = v[i].y - mu, dz = v[i].z - mu, dw = v[i].w - mu;
        sq += dx * dx + dy * dy + dz * dz + dw * dw;
    }
    #pragma unroll
    for (int o = 16; o > 0; o >>= 1) sq += __shfl_xor_sync(0xffffffffu, sq, o);
    float rstd = rsqrtf(sq / CC + 1e-5f);

    const float4* g4 = (const float4*)g;
    const float4* b4 = (const float4*)b;
    uint2* o2p = (uint2*)(out + (size_t)row * CC);
    #pragma unroll
    for (int i = 0; i < 6; i++) {
        int f4 = lane + i * 32;
        float4 gv = g4[f4], bv = b4[f4];
        float o0 = (v[i].x - mu) * rstd * gv.x + bv.x;
        float o1 = (v[i].y - mu) * rstd * gv.y + bv.y;
        float o2 = (v[i].z - mu) * rstd * gv.z + bv.z;
        float o3 = (v[i].w - mu) * rstd * gv.w + bv.w;
        uint2 w;
        w.x = packhf(o0, o1); w.y = packhf(o2, o3);
        o2p[f4] = w;
    }
}

// ---------------- flash attention (fp16: Q hi/lo, K/V single, P hi only) --
#define FA_STRIDE 144
#define FA_TILE   (64 * FA_STRIDE)
#define FA_KV0    (2 * FA_TILE)
#define FA_STAGE  (2 * FA_TILE)
#define FA_SMEM   (2 * FA_TILE + 2 * FA_STAGE)   // 55296

__global__ void __launch_bounds__(128, 4)
fattn_kernel(const __half* __restrict__ qh,
             const __half* __restrict__ ql,
             __half* __restrict__ outp) {
    extern __shared__ char fs[];
    uint32_t sb = smem_u32(fs);
    int qt = 15 - blockIdx.x;
    int bh = blockIdx.y;
    int h = bh % HH, b = bh / HH;
    int tid = threadIdx.x, lane = tid & 31, w = tid >> 5;
    int q0 = qt * 64;
    size_t boff = (size_t)b * TT * C3 + (size_t)h * 3 * HS;
    const __half* bhp = qh + boff;
    const __half* blp = ql + boff;

    int lrow = tid >> 1, lc = (tid & 1) * 32;
    uint32_t lso = (uint32_t)lrow * FA_STRIDE + (uint32_t)lc * 2;

    auto load_kv = [&](int kt, int s) {
        uint32_t base = sb + FA_KV0 + (uint32_t)s * FA_STAGE;
        size_t krow = (size_t)(kt * 64 + lrow) * C3 + lc;
        const char* kp = (const char*)(bhp + krow + HS);
        const char* vp = (const char*)(bhp + krow + 2 * HS);
        #pragma unroll
        for (int i = 0; i < 4; i++) {
            cp16(base + 0 * FA_TILE + lso + i * 16, kp + i * 16, 16);
            cp16(base + 1 * FA_TILE + lso + i * 16, vp + i * 16, 16);
        }
        cp_commit();
    };

    {
        const uint4* sh = (const uint4*)(bhp + (size_t)(q0 + lrow) * C3 + lc);
        const uint4* sl = (const uint4*)(blp + (size_t)(q0 + lrow) * C3 + lc);
        uint4* dh = (uint4*)(fs + 0 * FA_TILE + lrow * FA_STRIDE + lc * 2);
        uint4* dl = (uint4*)(fs + 1 * FA_TILE + lrow * FA_STRIDE + lc * 2);
        #pragma unroll
        for (int i = 0; i < 4; i++) { dh[i] = sh[i]; dl[i] = sl[i]; }
    }
    load_kv(0, 0);
    __syncthreads();

    int lr = lane & 15, lh = (lane >> 4) * 16;
    uint32_t qhf[4][4], qlf[4][4];
    #pragma unroll
    for (int kk = 0; kk < 4; kk++) {
        uint32_t ad = sb + 0 * FA_TILE + (uint32_t)(w * 16 + lr) * FA_STRIDE + kk * 32 + lh;
        ldsm4(qhf[kk], ad);
        ldsm4(qlf[kk], ad + FA_TILE);
    }

    uint32_t vrow_l = (uint32_t)((lane & 7) + ((lane >> 4) << 3));
    uint32_t vcol_l = (uint32_t)(((lane >> 3) & 1) * 16);

    int g = lane >> 2, tg = lane & 3;
    int r0 = q0 + w * 16 + g;
    float m0 = -1e30f, m1 = -1e30f, l0 = 0.f, l1 = 0.f;
    float O[8][4];
    #pragma unroll
    for (int f = 0; f < 8; f++)
        #pragma unroll
        for (int e = 0; e < 4; e++) O[f][e] = 0.f;

    for (int kt = 0; kt <= qt; kt++) {
        int buf = kt & 1;
        if (kt + 1 <= qt) {
            load_kv(kt + 1, buf ^ 1);
            asm volatile("cp.async.wait_group 1;" ::: "memory");
        } else {
            asm volatile("cp.async.wait_group 0;" ::: "memory");
        }
        __syncthreads();

        uint32_t stage = sb + FA_KV0 + (uint32_t)buf * FA_STAGE;

        float S[8][4];
        #pragma unroll
        for (int f = 0; f < 8; f++)
            #pragma unroll
            for (int e = 0; e < 4; e++) S[f][e] = 0.f;

        #pragma unroll
        for (int kk = 0; kk < 4; kk++) {
            #pragma unroll
            for (int nt = 0; nt < 4; nt++) {
                uint32_t bd = stage + (uint32_t)(nt * 16 + lr) * FA_STRIDE + kk * 32 + lh;
                uint32_t bf[4];
                ldsm4(bf, bd);
                #pragma unroll
                for (int sub = 0; sub < 2; sub++) {
                    float* d = S[nt * 2 + sub];
                    mma_fp16(d, qhf[kk], bf[sub], bf[sub + 2]);
                    mma_fp16(d, qlf[kk], bf[sub], bf[sub + 2]);
                }
            }
        }

        #pragma unroll
        for (int f = 0; f < 8; f++)
            #pragma unroll
            for (int e = 0; e < 4; e++) S[f][e] *= SCALE;
        if (kt == qt) {
            #pragma unroll
            for (int f = 0; f < 8; f++) {
                int colb = kt * 64 + f * 8 + tg * 2;
                if (colb     > r0)     S[f][0] = -1e30f;
                if (colb + 1 > r0)     S[f][1] = -1e30f;
                if (colb     > r0 + 8) S[f][2] = -1e30f;
                if (colb + 1 > r0 + 8) S[f][3] = -1e30f;
            }
        }

        float mx0 = -1e30f, mx1 = -1e30f;
        #pragma unroll
        for (int f = 0; f < 8; f++) {
            mx0 = fmaxf(mx0, fmaxf(S[f][0], S[f][1]));
            mx1 = fmaxf(mx1, fmaxf(S[f][2], S[f][3]));
        }
        mx0 = fmaxf(mx0, __shfl_xor_sync(0xffffffffu, mx0, 1));
        mx0 = fmaxf(mx0, __shfl_xor_sync(0xffffffffu, mx0, 2));
        mx1 = fmaxf(mx1, __shfl_xor_sync(0xffffffffu, mx1, 1));
        mx1 = fmaxf(mx1, __shfl_xor_sync(0xffffffffu, mx1, 2));

        float mn0 = fmaxf(m0, mx0), mn1 = fmaxf(m1, mx1);
        float sc0 = __expf(m0 - mn0), sc1 = __expf(m1 - mn1);
        m0 = mn0; m1 = mn1;
        l0 *= sc0; l1 *= sc1;
        #pragma unroll
        for (int f = 0; f < 8; f++) {
            O[f][0] *= sc0; O[f][1] *= sc0;
            O[f][2] *= sc1; O[f][3] *= sc1;
        }

        float ps0 = 0.f, ps1 = 0.f;
        #pragma unroll
        for (int f = 0; f < 8; f++) {
            S[f][0] = __expf(S[f][0] - m0);
            S[f][1] = __expf(S[f][1] - m0);
            S[f][2] = __expf(S[f][2] - m1);
            S[f][3] = __expf(S[f][3] - m1);
            ps0 += S[f][0] + S[f][1];
            ps1 += S[f][2] + S[f][3];
        }
        ps0 += __shfl_xor_sync(0xffffffffu, ps0, 1);
        ps0 += __shfl_xor_sync(0xffffffffu, ps0, 2);
        ps1 += __shfl_xor_sync(0xffffffffu, ps1, 1);
        ps1 += __shfl_xor_sync(0xffffffffu, ps1, 2);
        l0 += ps0; l1 += ps1;

        // ---- P fragments (fp16 hi only) ----
        uint32_t ph[4][4];
        #pragma unroll
        for (int kk = 0; kk < 4; kk++) {
            float* A0 = S[2 * kk];
            float* A1 = S[2 * kk + 1];
            ph[kk][0] = packhf(A0[0], A0[1]);
            ph[kk][1] = packhf(A0[2], A0[3]);
            ph[kk][2] = packhf(A1[0], A1[1]);
            ph[kk][3] = packhf(A1[2], A1[3]);
        }

        // ---- O += P V ----
        #pragma unroll
        for (int kk = 0; kk < 4; kk++) {
            uint32_t vr = (uint32_t)(kk * 16) + vrow_l;
            #pragma unroll
            for (int nt = 0; nt < 4; nt++) {
                uint32_t bd = stage + FA_TILE + vr * FA_STRIDE + (uint32_t)(nt * 32) + vcol_l;
                uint32_t bf[4];
                ldsm4t(bf, bd);
                #pragma unroll
                for (int sub = 0; sub < 2; sub++)
                    mma_fp16(O[nt * 2 + sub], ph[kk], bf[sub], bf[sub + 2]);
            }
        }
        __syncthreads();
    }

    float inv0 = 1.f / l0, inv1 = 1.f / l1;
    #pragma unroll
    for (int f = 0; f < 8; f++) {
        int col = h * HS + f * 8 + tg * 2;
        size_t i0 = ((size_t)(b * TT + r0)) * CC + col;
        size_t i1 = i0 + (size_t)8 * CC;
        *(uint32_t*)(outp + i0) = packhf(O[f][0] * inv0, O[f][1] * inv0);
        *(uint32_t*)(outp + i1) = packhf(O[f][2] * inv1, O[f][3] * inv1);
    }
}

// ---------------- batched weight transpose + fp16 hi/lo split -------------
__global__ void conv_wt_all_kernel(const float* __restrict__ W,
                                   __half* __restrict__ hi,
                                   __half* __restrict__ lo,
                                   int K, int N) {
    __shared__ float ts[32][33];
    size_t lstride = (size_t)K * N;
    const float* Wl = W + lstride * blockIdx.z;
    __half* hil = hi + lstride * blockIdx.z;
    __half* lol = lo + lstride * blockIdx.z;
    int k0 = blockIdx.y * 32, n0 = blockIdx.x * 32;
    int tx = threadIdx.x, ty = threadIdx.y;
    #pragma unroll
    for (int i = 0; i < 32; i += 8)
        ts[ty + i][tx] = Wl[(size_t)(k0 + ty + i) * N + n0 + tx];
    __syncthreads();
    #pragma unroll
    for (int i = 0; i < 32; i += 8) {
        float v = ts[tx][ty + i];
        size_t o = (size_t)(n0 + ty + i) * K + k0 + tx;
        __half h = __float2half(v);
        hil[o] = h;
        lol[o] = __float2half(v - __half2float(h));
    }
}

// ---------------- wte -> fp16 ----------------
__global__ void conv_hf_kernel(const float* __restrict__ x,
                               __half* __restrict__ out, size_t n) {
    size_t i = (size_t)blockIdx.x * blockDim.x + threadIdx.x;
    if (i < n) out[i] = __float2half(x[i]);
}

// ---------------- HMMA fp16x2 GEMM (internal), 3-stage pipeline ----------
#define TSTRIDE  80
#define T_A      0
#define T_B_HI   10240
#define T_B_LO   20480
#define T_STAGE  30720
#define GSMEM    (3 * T_STAGE)

__device__ __forceinline__ float gelu_f(float v) {
    return 0.5f * v * (1.0f + erff(v * 0.7071067811865475f));
}

// OUT: 0 = fp32 (+res), 1 = fp16 hi/lo (lo only for Q columns), 2 = fp16
template<int OUT, bool BIAS, bool GELU, bool RES>
__global__ void __launch_bounds__(256, 2)
gemm2_kernel(const __half* __restrict__ A,
             const __half* __restrict__ Bhi, const __half* __restrict__ Blo,
             const float* __restrict__ bias, const float* __restrict__ res,
             float* __restrict__ C,
             __half* __restrict__ Chi, __half* __restrict__ Clo,
             __half* __restrict__ Ch,
             int M, int N, int K) {
    extern __shared__ char smem[];
    uint32_t sb = smem_u32(smem);
    int tid = threadIdx.x;
    int lane = tid & 31, wid = tid >> 5;
    int wr = wid >> 1, wc = wid & 1;
    int row0 = blockIdx.y * 128, col0 = blockIdx.x * 128;

    const char* pA  = (const char*)A;
    const char* pBh = (const char*)Bhi;
    const char* pBl = (const char*)Blo;

    float acc[2][8][4];
    #pragma unroll
    for (int a = 0; a < 2; a++)
        #pragma unroll
        for (int b = 0; b < 8; b++)
            #pragma unroll
            for (int e = 0; e < 4; e++) acc[a][b][e] = 0.f;

    int nc = K / 32;
    size_t Kb = (size_t)K * 2;
    int l_row0 = tid >> 2;
    int l_p    = tid & 3;

    auto load_tile = [&](int c) {
        uint32_t s = sb + (uint32_t)(c % 3) * T_STAGE;
        size_t kb = (size_t)c * 64;
        #pragma unroll
        for (int i = 0; i < 2; i++) {
            int row = l_row0 + i * 64;
            uint32_t so = (uint32_t)row * TSTRIDE + (uint32_t)l_p * 16;
            size_t ao = (size_t)(row0 + row) * Kb + kb + (size_t)l_p * 16;
            cp16(s + T_A + so, pA + ao, 16);
            int nr = col0 + row;
            int v = (nr < N) ? 16 : 0;
            size_t bo = (size_t)((nr < N) ? nr : 0) * Kb + kb + (size_t)l_p * 16;
            cp16(s + T_B_HI + so, pBh + bo, v);
            cp16(s + T_B_LO + so, pBl + bo, v);
        }
        cp_commit();
    };

    load_tile(0);
    if (nc > 1) load_tile(1);

    int lr = lane & 15;
    int lh = (lane >> 4) * 16;

    for (int c = 0; c < nc; c++) {
        if (c + 1 < nc) {
            asm volatile("cp.async.wait_group 1;" ::: "memory");
        } else {
            asm volatile("cp.async.wait_group 0;" ::: "memory");
        }
        __syncthreads();
        if (c + 2 < nc) load_tile(c + 2);    // stage (c+2)%3, read last at c-1

        uint32_t s = sb + (uint32_t)(c % 3) * T_STAGE;
        #pragma unroll
        for (int ks = 0; ks < 2; ks++) {
            uint32_t ko = ks * 32;
            uint32_t ah[2][4];
            #pragma unroll
            for (int mt = 0; mt < 2; mt++) {
                uint32_t ad = s + T_A +
                              (uint32_t)(wr * 32 + mt * 16 + lr) * TSTRIDE + ko + lh;
                ldsm4(ah[mt], ad);
            }
            #pragma unroll
            for (int nt = 0; nt < 4; nt++) {
                uint32_t bd = s + T_B_HI +
                              (uint32_t)(wc * 64 + nt * 16 + lr) * TSTRIDE + ko + lh;
                uint32_t bh[4], bl[4];
                ldsm4(bh, bd);
                ldsm4(bl, bd + (T_B_LO - T_B_HI));
                #pragma unroll
                for (int mt = 0; mt < 2; mt++) {
                    #pragma unroll
                    for (int sub = 0; sub < 2; sub++) {
                        float* d = acc[mt][nt * 2 + sub];
                        mma_fp16(d, ah[mt], bh[sub], bh[sub + 2]);
                        mma_fp16(d, ah[mt], bl[sub], bl[sub + 2]);
                    }
                }
            }
        }
    }

    int g = lane >> 2, tg = lane & 3;
    #pragma unroll
    for (int mt = 0; mt < 2; mt++) {
        int r0g = row0 + wr * 32 + mt * 16 + g;
        #pragma unroll
        for (int n8 = 0; n8 < 8; n8++) {
            int gc = col0 + wc * 64 + n8 * 8 + tg * 2;
            if (gc + 1 >= N) continue;
            float* d = acc[mt][n8];
            float b0 = 0.f, b1 = 0.f;
            if (BIAS) { b0 = bias[gc]; b1 = bias[gc + 1]; }
            #pragma unroll
            for (int hf = 0; hf < 2; hf++) {
                int rr = r0g + hf * 8;
                float v0 = d[hf * 2] + b0;
                float v1 = d[hf * 2 + 1] + b1;
                if (GELU) { v0 = gelu_f(v0); v1 = gelu_f(v1); }
                size_t idx = (size_t)rr * N + gc;
                if (RES) { v0 += res[idx]; v1 += res[idx + 1]; }
                if (OUT == 1) {
                    *(uint32_t*)(Chi + idx) = packhf(v0, v1);
                    if ((gc % 192) < 64)
                        *(uint32_t*)(Clo + idx) = packhf(v0 - hfhi(v0), v1 - hfhi(v1));
                } else if (OUT == 2) {
                    *(uint32_t*)(Ch + idx) = packhf(v0, v1);
                } else {
                    float2 t; t.x = v0; t.y = v1;
                    *(float2*)(C + idx) = t;
                }
            }
        }
    }
}

// ---------------- HMMA fp16 GEMM (LM head; rows in x for L2 B reuse) ------
#define H_A      0
#define H_B      10240
#define H_STAGE  20480
#define GSMEMH   (2 * H_STAGE)

__global__ void __launch_bounds__(256, 2)
gemmh_kernel(const __half* __restrict__ A, const __half* __restrict__ B,
             float* __restrict__ C, int M, int N, int K) {
    extern __shared__ char smem[];
    uint32_t sb = smem_u32(smem);
    int tid = threadIdx.x;
    int lane = tid & 31, wid = tid >> 5;
    int wr = wid >> 1, wc = wid & 1;
    int row0 = blockIdx.x * 128, col0 = blockIdx.y * 128;

    const char* pA = (const char*)A;
    const char* pB = (const char*)B;

    float acc[2][8][4];
    #pragma unroll
    for (int a = 0; a < 2; a++)
        #pragma unroll
        for (int b = 0; b < 8; b++)
            #pragma unroll
            for (int e = 0; e < 4; e++) acc[a][b][e] = 0.f;

    int nc = K / 32;
    size_t Kb = (size_t)K * 2;
    int l_row0 = tid >> 2;
    int l_p    = tid & 3;

    auto load_tile = [&](int c) {
        uint32_t s = sb + (uint32_t)(c & 1) * H_STAGE;
        size_t kb = (size_t)c * 64;
        #pragma unroll
        for (int i = 0; i < 2; i++) {
            int row = l_row0 + i * 64;
            uint32_t so = (uint32_t)row * TSTRIDE + (uint32_t)l_p * 16;
            size_t ao = (size_t)(row0 + row) * Kb + kb + (size_t)l_p * 16;
            cp16(s + H_A + so, pA + ao, 16);
            int nr = col0 + row;
            int v = (nr < N) ? 16 : 0;
            size_t bo = (size_t)((nr < N) ? nr : 0) * Kb + kb + (size_t)l_p * 16;
            cp16(s + H_B + so, pB + bo, v);
        }
        cp_commit();
    };

    load_tile(0);

    int lr = lane & 15;
    int lh = (lane >> 4) * 16;

    for (int c = 0; c < nc; c++) {
        if (c + 1 < nc) {
            load_tile(c + 1);
            asm volatile("cp.async.wait_group 1;" ::: "memory");
        } else {
            asm volatile("cp.async.wait_group 0;" ::: "memory");
        }
        __syncthreads();

        uint32_t s = sb + (uint32_t)(c & 1) * H_STAGE;
        #pragma unroll
        for (int ks = 0; ks < 2; ks++) {
            uint32_t ko = ks * 32;
            uint32_t ah[2][4];
            #pragma unroll
            for (int mt = 0; mt < 2; mt++) {
                uint32_t ad = s + H_A +
                              (uint32_t)(wr * 32 + mt * 16 + lr) * TSTRIDE + ko + lh;
                ldsm4(ah[mt], ad);
            }
            #pragma unroll
            for (int nt = 0; nt < 4; nt++) {
                uint32_t bd = s + H_B +
                              (uint32_t)(wc * 64 + nt * 16 + lr) * TSTRIDE + ko + lh;
                uint32_t bf[4];
                ldsm4(bf, bd);
                #pragma unroll
                for (int mt = 0; mt < 2; mt++) {
                    #pragma unroll
                    for (int sub = 0; sub < 2; sub++)
                        mma_fp16(acc[mt][nt * 2 + sub], ah[mt], bf[sub], bf[sub + 2]);
                }
            }
        }
        __syncthreads();
    }

    int g = lane >> 2, tg = lane & 3;
    #pragma unroll
    for (int mt = 0; mt < 2; mt++) {
        int r0g = row0 + wr * 32 + mt * 16 + g;
        #pragma unroll
        for (int n8 = 0; n8 < 8; n8++) {
            int gc = col0 + wc * 64 + n8 * 8 + tg * 2;
            float* d = acc[mt][n8];
            #pragma unroll
            for (int e = 0; e < 4; e++) {
                int rr = r0g + ((e >= 2) ? 8 : 0);
                int cc_ = gc + (e & 1);
                if (cc_ < N) C[(size_t)rr * N + cc_] = d[e];
            }
        }
    }
}

// ---------------- host orchestration ----------------
template<int OUT, bool BIAS, bool GELU, bool RES>
static void gemm2(const __half* A, const __half* bhi, const __half* blo,
                  const float* bias, const float* res,
                  float* C, __half* Chi, __half* Clo, __half* Ch,
                  int M, int N, int K) {
    dim3 grid((N + 127) / 128, M / 128);
    gemm2_kernel<OUT, BIAS, GELU, RES><<<grid, 256, GSMEM>>>(
        A, bhi, blo, bias, res, C, Chi, Clo, Ch, M, N, K);
}

extern "C" void kernel_launch(void* const* d_in, const int* in_sizes, int n_in,
                              void* d_out, int out_size) {
    const int*   inp   = (const int*)  d_in[0];
    const float* wte   = (const float*)d_in[1];
    const float* wpe   = (const float*)d_in[2];
    const float* ln1_g = (const float*)d_in[3];
    const float* ln1_b = (const float*)d_in[4];
    const float* wqkv  = (const float*)d_in[5];
    const float* bqkv  = (const float*)d_in[6];
    const float* wout  = (const float*)d_in[7];
    const float* bout  = (const float*)d_in[8];
    const float* ln2_g = (const float*)d_in[9];
    const float* ln2_b = (const float*)d_in[10];
    const float* wfc1  = (const float*)d_in[11];
    const float* bfc1  = (const float*)d_in[12];
    const float* wfc2  = (const float*)d_in[13];
    const float* bfc2  = (const float*)d_in[14];
    const float* lnf_g = (const float*)d_in[15];
    const float* lnf_b = (const float*)d_in[16];
    float* logits = (float*)d_out;

    float *x;
    __half *qh, *ql, *af, *ff, *wh, *wl, *tef;
    cudaGetSymbolAddress((void**)&x,   g_x);
    cudaGetSymbolAddress((void**)&qh,  g_qh);
    cudaGetSymbolAddress((void**)&ql,  g_ql);
    cudaGetSymbolAddress((void**)&af,  g_af);
    cudaGetSymbolAddress((void**)&ff,  g_ff);
    cudaGetSymbolAddress((void**)&wh,  g_wh);
    cudaGetSymbolAddress((void**)&wl,  g_wl);
    cudaGetSymbolAddress((void**)&tef, g_tef);

    cudaFuncSetAttribute(gemm2_kernel<1, true, false, false>, cudaFuncAttributeMaxDynamicSharedMemorySize, GSMEM);
    cudaFuncSetAttribute(gemm2_kernel<0, true, false, true >, cudaFuncAttributeMaxDynamicSharedMemorySize, GSMEM);
    cudaFuncSetAttribute(gemm2_kernel<2, true, true,  false>, cudaFuncAttributeMaxDynamicSharedMemorySize, GSMEM);
    cudaFuncSetAttribute(gemmh_kernel, cudaFuncAttributeMaxDynamicSharedMemorySize, GSMEMH);
    cudaFuncSetAttribute(fattn_kernel, cudaFuncAttributeMaxDynamicSharedMemorySize, FA_SMEM);

    __half* wh_q = wh;
    __half* wh_o = wh_q + (size_t)NL * SZ_Q;
    __half* wh_1 = wh_o + (size_t)NL * SZ_O;
    __half* wh_2 = wh_1 + (size_t)NL * SZ_1;
    __half* wl_q = wl;
    __half* wl_o = wl_q + (size_t)NL * SZ_Q;
    __half* wl_1 = wl_o + (size_t)NL * SZ_O;
    __half* wl_2 = wl_1 + (size_t)NL * SZ_1;

    conv_wt_all_kernel<<<dim3(C3 / 32, CC / 32, NL), dim3(32, 8)>>>(wqkv, wh_q, wl_q, CC, C3);
    conv_wt_all_kernel<<<dim3(CC / 32, CC / 32, NL), dim3(32, 8)>>>(wout, wh_o, wl_o, CC, CC);
    conv_wt_all_kernel<<<dim3(C4 / 32, CC / 32, NL), dim3(32, 8)>>>(wfc1, wh_1, wl_1, CC, C4);
    conv_wt_all_kernel<<<dim3(CC / 32, C4 / 32, NL), dim3(32, 8)>>>(wfc2, wh_2, wl_2, C4, CC);
    conv_hf_kernel<<<(unsigned)(((size_t)VV * CC + 255) / 256), 256>>>(
        wte, tef, (size_t)VV * CC);

    embed_kernel<<<(BT * CC + 255) / 256, 256>>>(inp, wte, wpe, x);

    for (int l = 0; l < NL; l++) {
        const float* g1  = ln1_g + (size_t)l * CC;
        const float* b1  = ln1_b + (size_t)l * CC;
        const float* bq  = bqkv  + (size_t)l * C3;
        const float* bo  = bout  + (size_t)l * CC;
        const float* g2  = ln2_g + (size_t)l * CC;
        const float* b2  = ln2_b + (size_t)l * CC;
        const float* bb1 = bfc1  + (size_t)l * C4;
        const float* bb2 = bfc2  + (size_t)l * CC;

        ln_hf_kernel<<<BT / 8, 256>>>(x, g1, b1, af);
        gemm2<1, true, false, false>(af, wh_q + (size_t)l * SZ_Q, wl_q + (size_t)l * SZ_Q,
                                     bq, nullptr, nullptr, qh, ql, nullptr, BT, C3, CC);

        fattn_kernel<<<dim3(16, BB * HH), 128, FA_SMEM>>>(qh, ql, af);

        gemm2<0, true, false, true>(af, wh_o + (size_t)l * SZ_O, wl_o + (size_t)l * SZ_O,
                                    bo, x, x, nullptr, nullptr, nullptr, BT, CC, CC);

        ln_hf_kernel<<<BT / 8, 256>>>(x, g2, b2, af);
        gemm2<2, true, true, false>(af, wh_1 + (size_t)l * SZ_1, wl_1 + (size_t)l * SZ_1,
                                    bb1, nullptr, nullptr, nullptr, nullptr, ff, BT, C4, CC);

        gemm2<0, true, false, true>(ff, wh_2 + (size_t)l * SZ_2, wl_2 + (size_t)l * SZ_2,
                                    bb2, x, x, nullptr, nullptr, nullptr, BT, CC, C4);
    }

    ln_hf_kernel<<<BT / 8, 256>>>(x, lnf_g, lnf_b, af);
    {
        dim3 grid(BT / 128, (VV + 127) / 128);
        gemmh_kernel<<<grid, 256, GSMEMH>>>(af, tef, logits, BT, VV, CC);
    }
}

// round 17
// speedup vs baseline: 1.0455x; 1.0455x over previous
#include <cuda_runtime.h>
#include <cuda_bf16.h>
#include <cuda_fp16.h>
#include <math.h>
#include <stdint.h>

// ---------------- problem constants ----------------
#define NL   12
#define BB   4
#define TT   1024
#define CC   768
#define HH   12
#define HS   64
#define VV   50257
#define BT   (BB * TT)
#define C3   (3 * CC)
#define C4   (4 * CC)
#define SCALE 0.125f

#define SZ_Q  (CC * C3)
#define SZ_O  (CC * CC)
#define SZ_1  (CC * C4)
#define SZ_2  (C4 * CC)
#define SZ_ALL ((size_t)NL * (SZ_Q + SZ_O + SZ_1 + SZ_2))

// ---------------- device scratch ----------------
__device__ float g_x[BT * CC];
__device__ __half g_qh[BT * C3];
__device__ __half g_ql[BT * C3];
__device__ __half g_af[BT * CC];
__device__ __half g_ff[BT * C4];
__device__ __half g_wh[SZ_ALL];
__device__ __half g_wl[SZ_ALL];
__device__ __half g_tef[(size_t)VV * CC];

// ---------------- PTX helpers ----------------
__device__ __forceinline__ uint32_t smem_u32(const void* p) {
    uint32_t a;
    asm("{ .reg .u64 t; cvta.to.shared.u64 t, %1; cvt.u32.u64 %0, t; }" : "=r"(a) : "l"(p));
    return a;
}
__device__ __forceinline__ void cp16(uint32_t dst, const void* src, int sz) {
    asm volatile("cp.async.ca.shared.global [%0], [%1], 16, %2;"
                 :: "r"(dst), "l"(src), "r"(sz) : "memory");
}
__device__ __forceinline__ void cp_commit() {
    asm volatile("cp.async.commit_group;" ::: "memory");
}
__device__ __forceinline__ void ldsm4(uint32_t* r, uint32_t a) {
    asm volatile("ldmatrix.sync.aligned.m8n8.x4.shared.b16 {%0,%1,%2,%3}, [%4];"
                 : "=r"(r[0]), "=r"(r[1]), "=r"(r[2]), "=r"(r[3]) : "r"(a));
}
__device__ __forceinline__ void ldsm4t(uint32_t* r, uint32_t a) {
    asm volatile("ldmatrix.sync.aligned.m8n8.x4.trans.shared.b16 {%0,%1,%2,%3}, [%4];"
                 : "=r"(r[0]), "=r"(r[1]), "=r"(r[2]), "=r"(r[3]) : "r"(a));
}
__device__ __forceinline__ void mma_fp16(float* d, const uint32_t* a,
                                         uint32_t b0, uint32_t b1) {
    asm volatile(
        "mma.sync.aligned.m16n8k16.row.col.f32.f16.f16.f32 "
        "{%0,%1,%2,%3}, {%4,%5,%6,%7}, {%8,%9}, {%0,%1,%2,%3};"
        : "+f"(d[0]), "+f"(d[1]), "+f"(d[2]), "+f"(d[3])
        : "r"(a[0]), "r"(a[1]), "r"(a[2]), "r"(a[3]), "r"(b0), "r"(b1));
}
__device__ __forceinline__ uint32_t packhf(float a, float b) {
    __half2 t = __floats2half2_rn(a, b);
    return *reinterpret_cast<uint32_t*>(&t);
}
__device__ __forceinline__ float hfhi(float v) {
    return __half2float(__float2half(v));
}

// ---------------- embedding ----------------
__global__ void embed_kernel(const int* __restrict__ inp,
                             const float* __restrict__ wte,
                             const float* __restrict__ wpe,
                             float* __restrict__ x) {
    int i = blockIdx.x * blockDim.x + threadIdx.x;
    if (i >= BT * CC) return;
    int c = i % CC;
    int bt = i / CC;
    int t = bt % TT;
    int tok = inp[bt];
    x[i] = wte[(size_t)tok * CC + c] + wpe[(size_t)t * CC + c];
}

// ---------------- layernorm (warp per row) -> fp16 ----------------
__global__ void __launch_bounds__(256)
ln_hf_kernel(const float* __restrict__ in,
             const float* __restrict__ g,
             const float* __restrict__ b,
             __half* __restrict__ out) {
    int row = blockIdx.x * 8 + (threadIdx.x >> 5);
    int lane = threadIdx.x & 31;
    const float4* r4 = (const float4*)(in + (size_t)row * CC);

    float4 v[6];
    float s = 0.f;
    #pragma unroll
    for (int i = 0; i < 6; i++) {
        v[i] = r4[lane + i * 32];
        s += v[i].x + v[i].y + v[i].z + v[i].w;
    }
    #pragma unroll
    for (int o = 16; o > 0; o >>= 1) s += __shfl_xor_sync(0xffffffffu, s, o);
    float mu = s / CC;

    float sq = 0.f;
    #pragma unroll
    for (int i = 0; i < 6; i++) {
        float dx = v[i].x - mu, dy = v[i].y - mu, dz = v[i].z - mu, dw = v[i].w - mu;
        sq += dx * dx + dy * dy + dz * dz + dw * dw;
    }
    #pragma unroll
    for (int o = 16; o > 0; o >>= 1) sq += __shfl_xor_sync(0xffffffffu, sq, o);
    float rstd = rsqrtf(sq / CC + 1e-5f);

    const float4* g4 = (const float4*)g;
    const float4* b4 = (const float4*)b;
    uint2* o2p = (uint2*)(out + (size_t)row * CC);
    #pragma unroll
    for (int i = 0; i < 6; i++) {
        int f4 = lane + i * 32;
        float4 gv = g4[f4], bv = b4[f4];
        float o0 = (v[i].x - mu) * rstd * gv.x + bv.x;
        float o1 = (v[i].y - mu) * rstd * gv.y + bv.y;
        float o2 = (v[i].z - mu) * rstd * gv.z + bv.z;
        float o3 = (v[i].w - mu) * rstd * gv.w + bv.w;
        uint2 w;
        w.x = packhf(o0, o1); w.y = packhf(o2, o3);
        o2p[f4] = w;
    }
}

// ---------------- flash attention (fp16: Q hi/lo, K/V single, P hi only) --
#define FA_STRIDE 144
#define FA_TILE   (64 * FA_STRIDE)
#define FA_KV0    (2 * FA_TILE)
#define FA_STAGE  (2 * FA_TILE)
#define FA_SMEM   (2 * FA_TILE + 2 * FA_STAGE)   // 55296

__global__ void __launch_bounds__(128, 4)
fattn_kernel(const __half* __restrict__ qh,
             const __half* __restrict__ ql,
             __half* __restrict__ outp) {
    extern __shared__ char fs[];
    uint32_t sb = smem_u32(fs);
    int qt = 15 - blockIdx.x;
    int bh = blockIdx.y;
    int h = bh % HH, b = bh / HH;
    int tid = threadIdx.x, lane = tid & 31, w = tid >> 5;
    int q0 = qt * 64;
    size_t boff = (size_t)b * TT * C3 + (size_t)h * 3 * HS;
    const __half* bhp = qh + boff;
    const __half* blp = ql + boff;

    int lrow = tid >> 1, lc = (tid & 1) * 32;
    uint32_t lso = (uint32_t)lrow * FA_STRIDE + (uint32_t)lc * 2;

    auto load_kv = [&](int kt, int s) {
        uint32_t base = sb + FA_KV0 + (uint32_t)s * FA_STAGE;
        size_t krow = (size_t)(kt * 64 + lrow) * C3 + lc;
        const char* kp = (const char*)(bhp + krow + HS);
        const char* vp = (const char*)(bhp + krow + 2 * HS);
        #pragma unroll
        for (int i = 0; i < 4; i++) {
            cp16(base + 0 * FA_TILE + lso + i * 16, kp + i * 16, 16);
            cp16(base + 1 * FA_TILE + lso + i * 16, vp + i * 16, 16);
        }
        cp_commit();
    };

    {
        const uint4* sh = (const uint4*)(bhp + (size_t)(q0 + lrow) * C3 + lc);
        const uint4* sl = (const uint4*)(blp + (size_t)(q0 + lrow) * C3 + lc);
        uint4* dh = (uint4*)(fs + 0 * FA_TILE + lrow * FA_STRIDE + lc * 2);
        uint4* dl = (uint4*)(fs + 1 * FA_TILE + lrow * FA_STRIDE + lc * 2);
        #pragma unroll
        for (int i = 0; i < 4; i++) { dh[i] = sh[i]; dl[i] = sl[i]; }
    }
    load_kv(0, 0);
    __syncthreads();

    int lr = lane & 15, lh = (lane >> 4) * 16;
    uint32_t qhf[4][4], qlf[4][4];
    #pragma unroll
    for (int kk = 0; kk < 4; kk++) {
        uint32_t ad = sb + 0 * FA_TILE + (uint32_t)(w * 16 + lr) * FA_STRIDE + kk * 32 + lh;
        ldsm4(qhf[kk], ad);
        ldsm4(qlf[kk], ad + FA_TILE);
    }

    uint32_t vrow_l = (uint32_t)((lane & 7) + ((lane >> 4) << 3));
    uint32_t vcol_l = (uint32_t)(((lane >> 3) & 1) * 16);

    int g = lane >> 2, tg = lane & 3;
    int r0 = q0 + w * 16 + g;
    float m0 = -1e30f, m1 = -1e30f, l0 = 0.f, l1 = 0.f;
    float O[8][4];
    #pragma unroll
    for (int f = 0; f < 8; f++)
        #pragma unroll
        for (int e = 0; e < 4; e++) O[f][e] = 0.f;

    for (int kt = 0; kt <= qt; kt++) {
        int buf = kt & 1;
        if (kt + 1 <= qt) {
            load_kv(kt + 1, buf ^ 1);
            asm volatile("cp.async.wait_group 1;" ::: "memory");
        } else {
            asm volatile("cp.async.wait_group 0;" ::: "memory");
        }
        __syncthreads();

        uint32_t stage = sb + FA_KV0 + (uint32_t)buf * FA_STAGE;

        float S[8][4];
        #pragma unroll
        for (int f = 0; f < 8; f++)
            #pragma unroll
            for (int e = 0; e < 4; e++) S[f][e] = 0.f;

        #pragma unroll
        for (int kk = 0; kk < 4; kk++) {
            #pragma unroll
            for (int nt = 0; nt < 4; nt++) {
                uint32_t bd = stage + (uint32_t)(nt * 16 + lr) * FA_STRIDE + kk * 32 + lh;
                uint32_t bf[4];
                ldsm4(bf, bd);
                #pragma unroll
                for (int sub = 0; sub < 2; sub++) {
                    float* d = S[nt * 2 + sub];
                    mma_fp16(d, qhf[kk], bf[sub], bf[sub + 2]);
                    mma_fp16(d, qlf[kk], bf[sub], bf[sub + 2]);
                }
            }
        }

        #pragma unroll
        for (int f = 0; f < 8; f++)
            #pragma unroll
            for (int e = 0; e < 4; e++) S[f][e] *= SCALE;
        if (kt == qt) {
            #pragma unroll
            for (int f = 0; f < 8; f++) {
                int colb = kt * 64 + f * 8 + tg * 2;
                if (colb     > r0)     S[f][0] = -1e30f;
                if (colb + 1 > r0)     S[f][1] = -1e30f;
                if (colb     > r0 + 8) S[f][2] = -1e30f;
                if (colb + 1 > r0 + 8) S[f][3] = -1e30f;
            }
        }

        float mx0 = -1e30f, mx1 = -1e30f;
        #pragma unroll
        for (int f = 0; f < 8; f++) {
            mx0 = fmaxf(mx0, fmaxf(S[f][0], S[f][1]));
            mx1 = fmaxf(mx1, fmaxf(S[f][2], S[f][3]));
        }
        mx0 = fmaxf(mx0, __shfl_xor_sync(0xffffffffu, mx0, 1));
        mx0 = fmaxf(mx0, __shfl_xor_sync(0xffffffffu, mx0, 2));
        mx1 = fmaxf(mx1, __shfl_xor_sync(0xffffffffu, mx1, 1));
        mx1 = fmaxf(mx1, __shfl_xor_sync(0xffffffffu, mx1, 2));

        float mn0 = fmaxf(m0, mx0), mn1 = fmaxf(m1, mx1);
        float sc0 = __expf(m0 - mn0), sc1 = __expf(m1 - mn1);
        m0 = mn0; m1 = mn1;
        l0 *= sc0; l1 *= sc1;
        #pragma unroll
        for (int f = 0; f < 8; f++) {
            O[f][0] *= sc0; O[f][1] *= sc0;
            O[f][2] *= sc1; O[f][3] *= sc1;
        }

        float ps0 = 0.f, ps1 = 0.f;
        #pragma unroll
        for (int f = 0; f < 8; f++) {
            S[f][0] = __expf(S[f][0] - m0);
            S[f][1] = __expf(S[f][1] - m0);
            S[f][2] = __expf(S[f][2] - m1);
            S[f][3] = __expf(S[f][3] - m1);
            ps0 += S[f][0] + S[f][1];
            ps1 += S[f][2] + S[f][3];
        }
        ps0 += __shfl_xor_sync(0xffffffffu, ps0, 1);
        ps0 += __shfl_xor_sync(0xffffffffu, ps0, 2);
        ps1 += __shfl_xor_sync(0xffffffffu, ps1, 1);
        ps1 += __shfl_xor_sync(0xffffffffu, ps1, 2);
        l0 += ps0; l1 += ps1;

        // ---- P fragments (fp16 hi only) ----
        uint32_t ph[4][4];
        #pragma unroll
        for (int kk = 0; kk < 4; kk++) {
            float* A0 = S[2 * kk];
            float* A1 = S[2 * kk + 1];
            ph[kk][0] = packhf(A0[0], A0[1]);
            ph[kk][1] = packhf(A0[2], A0[3]);
            ph[kk][2] = packhf(A1[0], A1[1]);
            ph[kk][3] = packhf(A1[2], A1[3]);
        }

        // ---- O += P V ----
        #pragma unroll
        for (int kk = 0; kk < 4; kk++) {
            uint32_t vr = (uint32_t)(kk * 16) + vrow_l;
            #pragma unroll
            for (int nt = 0; nt < 4; nt++) {
                uint32_t bd = stage + FA_TILE + vr * FA_STRIDE + (uint32_t)(nt * 32) + vcol_l;
                uint32_t bf[4];
                ldsm4t(bf, bd);
                #pragma unroll
                for (int sub = 0; sub < 2; sub++)
                    mma_fp16(O[nt * 2 + sub], ph[kk], bf[sub], bf[sub + 2]);
            }
        }
        __syncthreads();
    }

    float inv0 = 1.f / l0, inv1 = 1.f / l1;
    #pragma unroll
    for (int f = 0; f < 8; f++) {
        int col = h * HS + f * 8 + tg * 2;
        size_t i0 = ((size_t)(b * TT + r0)) * CC + col;
        size_t i1 = i0 + (size_t)8 * CC;
        *(uint32_t*)(outp + i0) = packhf(O[f][0] * inv0, O[f][1] * inv0);
        *(uint32_t*)(outp + i1) = packhf(O[f][2] * inv1, O[f][3] * inv1);
    }
}

// ---------------- batched weight transpose + fp16 hi/lo split -------------
__global__ void conv_wt_all_kernel(const float* __restrict__ W,
                                   __half* __restrict__ hi,
                                   __half* __restrict__ lo,
                                   int K, int N) {
    __shared__ float ts[32][33];
    size_t lstride = (size_t)K * N;
    const float* Wl = W + lstride * blockIdx.z;
    __half* hil = hi + lstride * blockIdx.z;
    __half* lol = lo + lstride * blockIdx.z;
    int k0 = blockIdx.y * 32, n0 = blockIdx.x * 32;
    int tx = threadIdx.x, ty = threadIdx.y;
    #pragma unroll
    for (int i = 0; i < 32; i += 8)
        ts[ty + i][tx] = Wl[(size_t)(k0 + ty + i) * N + n0 + tx];
    __syncthreads();
    #pragma unroll
    for (int i = 0; i < 32; i += 8) {
        float v = ts[tx][ty + i];
        size_t o = (size_t)(n0 + ty + i) * K + k0 + tx;
        __half h = __float2half(v);
        hil[o] = h;
        lol[o] = __float2half(v - __half2float(h));
    }
}

// ---------------- wte -> fp16 ----------------
__global__ void conv_hf_kernel(const float* __restrict__ x,
                               __half* __restrict__ out, size_t n) {
    size_t i = (size_t)blockIdx.x * blockDim.x + threadIdx.x;
    if (i < n) out[i] = __float2half(x[i]);
}

// ---------------- HMMA fp16x2 GEMM (internal), 2-stage double buffer -----
#define TSTRIDE  80
#define T_A      0
#define T_B_HI   10240
#define T_B_LO   20480
#define T_STAGE  30720
#define GSMEM    (2 * T_STAGE)

__device__ __forceinline__ float gelu_f(float v) {
    return 0.5f * v * (1.0f + erff(v * 0.7071067811865475f));
}

// OUT: 0 = fp32 (+res), 1 = fp16 hi/lo (lo only for Q columns), 2 = fp16
template<int OUT, bool BIAS, bool GELU, bool RES>
__global__ void __launch_bounds__(256, 2)
gemm2_kernel(const __half* __restrict__ A,
             const __half* __restrict__ Bhi, const __half* __restrict__ Blo,
             const float* __restrict__ bias, const float* __restrict__ res,
             float* __restrict__ C,
             __half* __restrict__ Chi, __half* __restrict__ Clo,
             __half* __restrict__ Ch,
             int M, int N, int K) {
    extern __shared__ char smem[];
    uint32_t sb = smem_u32(smem);
    int tid = threadIdx.x;
    int lane = tid & 31, wid = tid >> 5;
    int wr = wid >> 1, wc = wid & 1;
    int row0 = blockIdx.y * 128, col0 = blockIdx.x * 128;

    const char* pA  = (const char*)A;
    const char* pBh = (const char*)Bhi;
    const char* pBl = (const char*)Blo;

    float acc[2][8][4];
    #pragma unroll
    for (int a = 0; a < 2; a++)
        #pragma unroll
        for (int b = 0; b < 8; b++)
            #pragma unroll
            for (int e = 0; e < 4; e++) acc[a][b][e] = 0.f;

    int nc = K / 32;
    size_t Kb = (size_t)K * 2;
    int l_row0 = tid >> 2;
    int l_p    = tid & 3;

    auto load_tile = [&](int c) {
        uint32_t s = sb + (uint32_t)(c & 1) * T_STAGE;
        size_t kb = (size_t)c * 64;
        #pragma unroll
        for (int i = 0; i < 2; i++) {
            int row = l_row0 + i * 64;
            uint32_t so = (uint32_t)row * TSTRIDE + (uint32_t)l_p * 16;
            size_t ao = (size_t)(row0 + row) * Kb + kb + (size_t)l_p * 16;
            cp16(s + T_A + so, pA + ao, 16);
            int nr = col0 + row;
            int v = (nr < N) ? 16 : 0;
            size_t bo = (size_t)((nr < N) ? nr : 0) * Kb + kb + (size_t)l_p * 16;
            cp16(s + T_B_HI + so, pBh + bo, v);
            cp16(s + T_B_LO + so, pBl + bo, v);
        }
        cp_commit();
    };

    load_tile(0);

    int lr = lane & 15;
    int lh = (lane >> 4) * 16;

    for (int c = 0; c < nc; c++) {
        if (c + 1 < nc) {
            load_tile(c + 1);
            asm volatile("cp.async.wait_group 1;" ::: "memory");
        } else {
            asm volatile("cp.async.wait_group 0;" ::: "memory");
        }
        __syncthreads();

        uint32_t s = sb + (uint32_t)(c & 1) * T_STAGE;
        #pragma unroll
        for (int ks = 0; ks < 2; ks++) {
            uint32_t ko = ks * 32;
            uint32_t ah[2][4];
            #pragma unroll
            for (int mt = 0; mt < 2; mt++) {
                uint32_t ad = s + T_A +
                              (uint32_t)(wr * 32 + mt * 16 + lr) * TSTRIDE + ko + lh;
                ldsm4(ah[mt], ad);
            }
            #pragma unroll
            for (int nt = 0; nt < 4; nt++) {
                uint32_t bd = s + T_B_HI +
                              (uint32_t)(wc * 64 + nt * 16 + lr) * TSTRIDE + ko + lh;
                uint32_t bh[4], bl[4];
                ldsm4(bh, bd);
                ldsm4(bl, bd + (T_B_LO - T_B_HI));
                #pragma unroll
                for (int mt = 0; mt < 2; mt++) {
                    #pragma unroll
                    for (int sub = 0; sub < 2; sub++) {
                        float* d = acc[mt][nt * 2 + sub];
                        mma_fp16(d, ah[mt], bh[sub], bh[sub + 2]);
                        mma_fp16(d, ah[mt], bl[sub], bl[sub + 2]);
                    }
                }
            }
        }
        __syncthreads();
    }

    int g = lane >> 2, tg = lane & 3;
    #pragma unroll
    for (int mt = 0; mt < 2; mt++) {
        int r0g = row0 + wr * 32 + mt * 16 + g;
        #pragma unroll
        for (int n8 = 0; n8 < 8; n8++) {
            int gc = col0 + wc * 64 + n8 * 8 + tg * 2;
            if (gc + 1 >= N) continue;
            float* d = acc[mt][n8];
            float b0 = 0.f, b1 = 0.f;
            if (BIAS) { b0 = bias[gc]; b1 = bias[gc + 1]; }
            #pragma unroll
            for (int hf = 0; hf < 2; hf++) {
                int rr = r0g + hf * 8;
                float v0 = d[hf * 2] + b0;
                float v1 = d[hf * 2 + 1] + b1;
                if (GELU) { v0 = gelu_f(v0); v1 = gelu_f(v1); }
                size_t idx = (size_t)rr * N + gc;
                if (RES) { v0 += res[idx]; v1 += res[idx + 1]; }
                if (OUT == 1) {
                    *(uint32_t*)(Chi + idx) = packhf(v0, v1);
                    if ((gc % 192) < 64)
                        *(uint32_t*)(Clo + idx) = packhf(v0 - hfhi(v0), v1 - hfhi(v1));
                } else if (OUT == 2) {
                    *(uint32_t*)(Ch + idx) = packhf(v0, v1);
                } else {
                    float2 t; t.x = v0; t.y = v1;
                    *(float2*)(C + idx) = t;
                }
            }
        }
    }
}

// ---------------- HMMA fp16 GEMM (LM head; rows in x for L2 B reuse) ------
#define H_A      0
#define H_B      10240
#define H_STAGE  20480
#define GSMEMH   (2 * H_STAGE)

__global__ void __launch_bounds__(256, 2)
gemmh_kernel(const __half* __restrict__ A, const __half* __restrict__ B,
             float* __restrict__ C, int M, int N, int K) {
    extern __shared__ char smem[];
    uint32_t sb = smem_u32(smem);
    int tid = threadIdx.x;
    int lane = tid & 31, wid = tid >> 5;
    int wr = wid >> 1, wc = wid & 1;
    int row0 = blockIdx.x * 128, col0 = blockIdx.y * 128;

    const char* pA = (const char*)A;
    const char* pB = (const char*)B;

    float acc[2][8][4];
    #pragma unroll
    for (int a = 0; a < 2; a++)
        #pragma unroll
        for (int b = 0; b < 8; b++)
            #pragma unroll
            for (int e = 0; e < 4; e++) acc[a][b][e] = 0.f;

    int nc = K / 32;
    size_t Kb = (size_t)K * 2;
    int l_row0 = tid >> 2;
    int l_p    = tid & 3;

    auto load_tile = [&](int c) {
        uint32_t s = sb + (uint32_t)(c & 1) * H_STAGE;
        size_t kb = (size_t)c * 64;
        #pragma unroll
        for (int i = 0; i < 2; i++) {
            int row = l_row0 + i * 64;
            uint32_t so = (uint32_t)row * TSTRIDE + (uint32_t)l_p * 16;
            size_t ao = (size_t)(row0 + row) * Kb + kb + (size_t)l_p * 16;
            cp16(s + H_A + so, pA + ao, 16);
            int nr = col0 + row;
            int v = (nr < N) ? 16 : 0;
            size_t bo = (size_t)((nr < N) ? nr : 0) * Kb + kb + (size_t)l_p * 16;
            cp16(s + H_B + so, pB + bo, v);
        }
        cp_commit();
    };

    load_tile(0);

    int lr = lane & 15;
    int lh = (lane >> 4) * 16;

    for (int c = 0; c < nc; c++) {
        if (c + 1 < nc) {
            load_tile(c + 1);
            asm volatile("cp.async.wait_group 1;" ::: "memory");
        } else {
            asm volatile("cp.async.wait_group 0;" ::: "memory");
        }
        __syncthreads();

        uint32_t s = sb + (uint32_t)(c & 1) * H_STAGE;
        #pragma unroll
        for (int ks = 0; ks < 2; ks++) {
            uint32_t ko = ks * 32;
            uint32_t ah[2][4];
            #pragma unroll
            for (int mt = 0; mt < 2; mt++) {
                uint32_t ad = s + H_A +
                              (uint32_t)(wr * 32 + mt * 16 + lr) * TSTRIDE + ko + lh;
                ldsm4(ah[mt], ad);
            }
            #pragma unroll
            for (int nt = 0; nt < 4; nt++) {
                uint32_t bd = s + H_B +
                              (uint32_t)(wc * 64 + nt * 16 + lr) * TSTRIDE + ko + lh;
                uint32_t bf[4];
                ldsm4(bf, bd);
                #pragma unroll
                for (int mt = 0; mt < 2; mt++) {
                    #pragma unroll
                    for (int sub = 0; sub < 2; sub++)
                        mma_fp16(acc[mt][nt * 2 + sub], ah[mt], bf[sub], bf[sub + 2]);
                }
            }
        }
        __syncthreads();
    }

    int g = lane >> 2, tg = lane & 3;
    #pragma unroll
    for (int mt = 0; mt < 2; mt++) {
        int r0g = row0 + wr * 32 + mt * 16 + g;
        #pragma unroll
        for (int n8 = 0; n8 < 8; n8++) {
            int gc = col0 + wc * 64 + n8 * 8 + tg * 2;
            float* d = acc[mt][n8];
            #pragma unroll
            for (int e = 0; e < 4; e++) {
                int rr = r0g + ((e >= 2) ? 8 : 0);
                int cc_ = gc + (e & 1);
                if (cc_ < N) C[(size_t)rr * N + cc_] = d[e];
            }
        }
    }
}

// ---------------- host orchestration ----------------
template<int OUT, bool BIAS, bool GELU, bool RES>
static void gemm2(const __half* A, const __half* bhi, const __half* blo,
                  const float* bias, const float* res,
                  float* C, __half* Chi, __half* Clo, __half* Ch,
                  int M, int N, int K) {
    dim3 grid((N + 127) / 128, M / 128);
    gemm2_kernel<OUT, BIAS, GELU, RES><<<grid, 256, GSMEM>>>(
        A, bhi, blo, bias, res, C, Chi, Clo, Ch, M, N, K);
}

extern "C" void kernel_launch(void* const* d_in, const int* in_sizes, int n_in,
                              void* d_out, int out_size) {
    const int*   inp   = (const int*)  d_in[0];
    const float* wte   = (const float*)d_in[1];
    const float* wpe   = (const float*)d_in[2];
    const float* ln1_g = (const float*)d_in[3];
    const float* ln1_b = (const float*)d_in[4];
    const float* wqkv  = (const float*)d_in[5];
    const float* bqkv  = (const float*)d_in[6];
    const float* wout  = (const float*)d_in[7];
    const float* bout  = (const float*)d_in[8];
    const float* ln2_g = (const float*)d_in[9];
    const float* ln2_b = (const float*)d_in[10];
    const float* wfc1  = (const float*)d_in[11];
    const float* bfc1  = (const float*)d_in[12];
    const float* wfc2  = (const float*)d_in[13];
    const float* bfc2  = (const float*)d_in[14];
    const float* lnf_g = (const float*)d_in[15];
    const float* lnf_b = (const float*)d_in[16];
    float* logits = (float*)d_out;

    float *x;
    __half *qh, *ql, *af, *ff, *wh, *wl, *tef;
    cudaGetSymbolAddress((void**)&x,   g_x);
    cudaGetSymbolAddress((void**)&qh,  g_qh);
    cudaGetSymbolAddress((void**)&ql,  g_ql);
    cudaGetSymbolAddress((void**)&af,  g_af);
    cudaGetSymbolAddress((void**)&ff,  g_ff);
    cudaGetSymbolAddress((void**)&wh,  g_wh);
    cudaGetSymbolAddress((void**)&wl,  g_wl);
    cudaGetSymbolAddress((void**)&tef, g_tef);

    cudaFuncSetAttribute(gemm2_kernel<1, true, false, false>, cudaFuncAttributeMaxDynamicSharedMemorySize, GSMEM);
    cudaFuncSetAttribute(gemm2_kernel<0, true, false, true >, cudaFuncAttributeMaxDynamicSharedMemorySize, GSMEM);
    cudaFuncSetAttribute(gemm2_kernel<2, true, true,  false>, cudaFuncAttributeMaxDynamicSharedMemorySize, GSMEM);
    cudaFuncSetAttribute(gemmh_kernel, cudaFuncAttributeMaxDynamicSharedMemorySize, GSMEMH);
    cudaFuncSetAttribute(fattn_kernel, cudaFuncAttributeMaxDynamicSharedMemorySize, FA_SMEM);

    __half* wh_q = wh;
    __half* wh_o = wh_q + (size_t)NL * SZ_Q;
    __half* wh_1 = wh_o + (size_t)NL * SZ_O;
    __half* wh_2 = wh_1 + (size_t)NL * SZ_1;
    __half* wl_q = wl;
    __half* wl_o = wl_q + (size_t)NL * SZ_Q;
    __half* wl_1 = wl_o + (size_t)NL * SZ_O;
    __half* wl_2 = wl_1 + (size_t)NL * SZ_1;

    conv_wt_all_kernel<<<dim3(C3 / 32, CC / 32, NL), dim3(32, 8)>>>(wqkv, wh_q, wl_q, CC, C3);
    conv_wt_all_kernel<<<dim3(CC / 32, CC / 32, NL), dim3(32, 8)>>>(wout, wh_o, wl_o, CC, CC);
    conv_wt_all_kernel<<<dim3(C4 / 32, CC / 32, NL), dim3(32, 8)>>>(wfc1, wh_1, wl_1, CC, C4);
    conv_wt_all_kernel<<<dim3(CC / 32, C4 / 32, NL), dim3(32, 8)>>>(wfc2, wh_2, wl_2, C4, CC);
    conv_hf_kernel<<<(unsigned)(((size_t)VV * CC + 255) / 256), 256>>>(
        wte, tef, (size_t)VV * CC);

    embed_kernel<<<(BT * CC + 255) / 256, 256>>>(inp, wte, wpe, x);

    for (int l = 0; l < NL; l++) {
        const float* g1  = ln1_g + (size_t)l * CC;
        const float* b1  = ln1_b + (size_t)l * CC;
        const float* bq  = bqkv  + (size_t)l * C3;
        const float* bo  = bout  + (size_t)l * CC;
        const float* g2  = ln2_g + (size_t)l * CC;
        const float* b2  = ln2_b + (size_t)l * CC;
        const float* bb1 = bfc1  + (size_t)l * C4;
        const float* bb2 = bfc2  + (size_t)l * CC;

        ln_hf_kernel<<<BT / 8, 256>>>(x, g1, b1, af);
        gemm2<1, true, false, false>(af, wh_q + (size_t)l * SZ_Q, wl_q + (size_t)l * SZ_Q,
                                     bq, nullptr, nullptr, qh, ql, nullptr, BT, C3, CC);

        fattn_kernel<<<dim3(16, BB * HH), 128, FA_SMEM>>>(qh, ql, af);

        gemm2<0, true, false, true>(af, wh_o + (size_t)l * SZ_O, wl_o + (size_t)l * SZ_O,
                                    bo, x, x, nullptr, nullptr, nullptr, BT, CC, CC);

        ln_hf_kernel<<<BT / 8, 256>>>(x, g2, b2, af);
        gemm2<2, true, true, false>(af, wh_1 + (size_t)l * SZ_1, wl_1 + (size_t)l * SZ_1,
                                    bb1, nullptr, nullptr, nullptr, nullptr, ff, BT, C4, CC);

        gemm2<0, true, false, true>(ff, wh_2 + (size_t)l * SZ_2, wl_2 + (size_t)l * SZ_2,
                                    bb2, x, x, nullptr, nullptr, nullptr, BT, CC, C4);
    }

    ln_hf_kernel<<<BT / 8, 256>>>(x, lnf_g, lnf_b, af);
    {
        dim3 grid(BT / 128, (VV + 127) / 128);
        gemmh_kernel<<<grid, 256, GSMEMH>>>(af, tef, logits, BT, VV, CC);
    }
}